// round 17
// baseline (speedup 1.0000x reference)
#include <cuda_runtime.h>

// VectorQuantizer: x [32,64,64,64] f32 (B,C,H,W), emb [512,64] f32.
// For each of N=32*64*64 pixels, argmin_k ||x - e_k||^2, write e_k back.
//
// NUMERICS (validated R6/R11/R12, rel_err = 0.0 — DO NOT PERTURB):
//   s_k = __fsub_rn( __fadd_rn(x_sq, e_sq_k), __fmul_rn(2, dot_k) )
//   x_sq / e_sq: fl(v*v) then SEQUENTIAL fp32 adds, ascending index
//   dot_k: single FMA chain, ascending d (f32x2 lane == fmaf bit-exact)
//   argmin: strict < with ascending k (first-occurrence, jnp semantics)
//
// R12 post-mortem: ptxas SPLIT the dup-operand FFMA2 (mov {e,e} + fma.f32x2)
// back into 2 scalar FFMAs -> scalar-FFMA ceiling (2/cyc/SM, ~226us floor).
// This version makes both FFMA2 source pairs genuinely distinct:
//   lanes = two adjacent CODES; e-pair {e_k[d], e_k1[d]} loaded directly as
//   16B from a d-major (transposed) smem tile (zero movs, no duplication);
//   x-broadcast {x[d],x[d]} built once per d, reused by 16 FFMA2s.
// 2 pixels per thread (sequential accs) keeps the R12 LDS amortization.

#define KCODES 512
#define DIM    64
#define HW     4096        // 64*64 pixels per batch image
#define TILE   64          // threads per block
#define PXB    128         // pixels per block (2 adjacent px per thread)
#define KCHUNK 64          // codes staged in smem per chunk (16 KB)
#define GK     16          // codes per inner group (8 pairs)

__device__ float g_esq[KCODES];
__device__ float g_embT[DIM * KCODES];   // transposed codebook [d][k], 128 KB

__global__ void esq_kernel(const float* __restrict__ emb) {
    int k = blockIdx.x * blockDim.x + threadIdx.x;
    if (k < KCODES) {
        const float* e = emb + k * DIM;
        float s = 0.f;
#pragma unroll
        for (int d = 0; d < DIM; ++d)
            s = __fadd_rn(s, __fmul_rn(e[d], e[d]));   // mul-then-add, sequential
        g_esq[k] = s;
    }
}

// emb_T[d][k] = emb[k][d]; one block per d, coalesced writes.
__global__ void transpose_kernel(const float* __restrict__ emb) {
    const int d = blockIdx.x;
    const int k = threadIdx.x;
    g_embT[d * KCODES + k] = emb[k * DIM + d];
}

__global__ void __launch_bounds__(TILE) vq_kernel(
    const float* __restrict__ x,
    const float* __restrict__ emb,
    float* __restrict__ out)
{
    __shared__ float eT_s[DIM * KCHUNK];   // [d][k] d-major, row 256B, 16 KB
    __shared__ float esq_s[KCHUNK];

    const int tile = blockIdx.x;                 // 0..1023
    const int b    = tile >> 5;                  // 32 tiles (128 px) per image
    const int px0  = ((tile & 31) * PXB) + (threadIdx.x << 1);

    const float* xb = x + (size_t)b * DIM * HW + px0;

    // Two adjacent pixels per thread; keep per-channel halves addressable.
    float2 xv[DIM];                              // .x = pixel A, .y = pixel B
    float xsqA = 0.f, xsqB = 0.f;
#pragma unroll
    for (int c = 0; c < DIM; ++c) {
        const float2 v = *(const float2*)(xb + (size_t)c * HW);
        xsqA = __fadd_rn(xsqA, __fmul_rn(v.x, v.x));   // sequential, ascending c
        xsqB = __fadd_rn(xsqB, __fmul_rn(v.y, v.y));
        xv[c] = v;
    }

    float bestA = 3.4e38f, bestB = 3.4e38f;
    int   biA = 0, biB = 0;

    for (int chunk = 0; chunk < KCODES / KCHUNK; ++chunk) {
        __syncthreads();   // previous chunk's readers done before overwrite

        // Stage transposed tile: row d holds codes [chunk*64 .. +63].
        // Straight coalesced float4 copies; conflict-free STS.
        {
            const float4* srcT = (const float4*)g_embT;
#pragma unroll
            for (int j = 0; j < (DIM * KCHUNK / 4) / TILE; ++j) {   // 16
                const int i  = threadIdx.x + j * TILE;              // 0..1023
                const int d  = i >> 4;                              // /16
                const int k4 = i & 15;
                ((float4*)eT_s)[d * (KCHUNK / 4) + k4] =
                    srcT[d * (KCODES / 4) + chunk * (KCHUNK / 4) + k4];
            }
            esq_s[threadIdx.x] = g_esq[chunk * KCHUNK + threadIdx.x];
        }
        __syncthreads();

        const int kbase = chunk * KCHUNK;

        for (int g = 0; g < KCHUNK / GK; ++g) {          // 4 groups of 16 codes
            const int kb = g * GK;

            // 8 code-pair accumulators per pixel: lane0 = even code, lane1 = odd.
            unsigned long long aA[GK / 2], aB[GK / 2];
#pragma unroll
            for (int p = 0; p < GK / 2; ++p) { aA[p] = 0ull; aB[p] = 0ull; }

#pragma unroll 8
            for (int d = 0; d < DIM; ++d) {
                // x broadcast pairs {x,x}: 2 movs per d, reused by 16 FFMA2s.
                unsigned long long dA, dB;
                asm("mov.b64 %0, {%1, %1};" : "=l"(dA) : "f"(xv[d].x));
                asm("mov.b64 %0, {%1, %1};" : "=l"(dB) : "f"(xv[d].y));

                const float* row = eT_s + d * KCHUNK + kb;
#pragma unroll
                for (int q = 0; q < GK / 4; ++q) {       // 4 x 16B = 16 codes
                    // {e_k[d], e_k+1[d]} , {e_k+2[d], e_k+3[d]} directly from smem
                    const ulonglong2 P = *(const ulonglong2*)(row + 4 * q);
                    asm("fma.rn.f32x2 %0, %1, %2, %0;"
                        : "+l"(aA[2 * q + 0]) : "l"(P.x), "l"(dA));
                    asm("fma.rn.f32x2 %0, %1, %2, %0;"
                        : "+l"(aA[2 * q + 1]) : "l"(P.y), "l"(dA));
                    asm("fma.rn.f32x2 %0, %1, %2, %0;"
                        : "+l"(aB[2 * q + 0]) : "l"(P.x), "l"(dB));
                    asm("fma.rn.f32x2 %0, %1, %2, %0;"
                        : "+l"(aB[2 * q + 1]) : "l"(P.y), "l"(dB));
                }
            }

            // Unpack dots and run the frozen rounding pipeline, ascending k.
#pragma unroll
            for (int p = 0; p < GK / 2; ++p) {
                float dA0, dA1, dB0, dB1;
                asm("mov.b64 {%0, %1}, %2;" : "=f"(dA0), "=f"(dA1) : "l"(aA[p]));
                asm("mov.b64 {%0, %1}, %2;" : "=f"(dB0), "=f"(dB1) : "l"(aB[p]));
                const int k0 = kbase + kb + 2 * p;
                const float q0 = esq_s[kb + 2 * p + 0];
                const float q1 = esq_s[kb + 2 * p + 1];

                const float sA0 = __fsub_rn(__fadd_rn(xsqA, q0), __fmul_rn(2.f, dA0));
                const float sA1 = __fsub_rn(__fadd_rn(xsqA, q1), __fmul_rn(2.f, dA1));
                if (sA0 < bestA) { bestA = sA0; biA = k0 + 0; }
                if (sA1 < bestA) { bestA = sA1; biA = k0 + 1; }

                const float sB0 = __fsub_rn(__fadd_rn(xsqB, q0), __fmul_rn(2.f, dB0));
                const float sB1 = __fsub_rn(__fadd_rn(xsqB, q1), __fmul_rn(2.f, dB1));
                if (sB0 < bestB) { bestB = sB0; biB = k0 + 0; }
                if (sB1 < bestB) { bestB = sB1; biB = k0 + 1; }
            }
        }
    }

    // Gather winning codes (L2-hot) and scatter both pixels with float2 stores.
    const float* eA = emb + (size_t)biA * DIM;
    const float* eB = emb + (size_t)biB * DIM;
    float* ob = out + (size_t)b * DIM * HW + px0;
#pragma unroll
    for (int q = 0; q < DIM / 4; ++q) {
        const float4 va = ((const float4*)eA)[q];
        const float4 vb = ((const float4*)eB)[q];
        *(float2*)(ob + (size_t)(4 * q + 0) * HW) = make_float2(va.x, vb.x);
        *(float2*)(ob + (size_t)(4 * q + 1) * HW) = make_float2(va.y, vb.y);
        *(float2*)(ob + (size_t)(4 * q + 2) * HW) = make_float2(va.z, vb.z);
        *(float2*)(ob + (size_t)(4 * q + 3) * HW) = make_float2(va.w, vb.w);
    }
}

extern "C" void kernel_launch(void* const* d_in, const int* in_sizes, int n_in,
                              void* d_out, int out_size) {
    const float* x   = (const float*)d_in[0];   // [32,64,64,64]
    const float* emb = (const float*)d_in[1];   // [512,64]
    float* out = (float*)d_out;                 // [32,64,64,64]

    esq_kernel<<<1, KCODES>>>(emb);
    transpose_kernel<<<DIM, KCODES>>>(emb);

    const int n_tiles = (32 * HW) / PXB;        // 1024 blocks, 128 px each
    vq_kernel<<<n_tiles, TILE>>>(x, emb, out);
}